// round 4
// baseline (speedup 1.0000x reference)
#include <cuda_runtime.h>
#include <stdint.h>

#define BATCH 4096
#define INDIM 1024
#define OUTDIM 1024
#define ELL_PAD 128            // slots per output column (mean 51, ~11 sigma headroom)

// -------- device scratch (static; no allocations allowed) --------
__device__ float g_inT[(size_t)INDIM * BATCH];          // transposed input, 16MB
__device__ uint2 g_meta[(size_t)OUTDIM * ELL_PAD];      // ELL: {weight bits, ind_in} per out col
__device__ int   g_cnt[OUTDIM];

// -------- 1. zero per-column counters --------
__global__ void k_zero() {
    g_cnt[threadIdx.x] = 0;
}

// -------- 2. ELL fill: one atomic gives the slot directly --------
__global__ void k_fill(const int* __restrict__ ind_in, const int* __restrict__ ind_out,
                       const float* __restrict__ wgt, int nnz) {
    int i = blockIdx.x * blockDim.x + threadIdx.x;
    if (i < nnz) {
        int o = ind_out[i];
        int r = atomicAdd(&g_cnt[o], 1);
        if (r < ELL_PAD)
            g_meta[o * ELL_PAD + r] = make_uint2(__float_as_uint(wgt[i]), (unsigned)ind_in[i]);
    }
}

// -------- 3. transpose input [4096,1024] -> inT [1024,4096] --------
__global__ void k_transpose(const float* __restrict__ in) {
    __shared__ float tile[32][33];
    int x  = blockIdx.x * 32 + threadIdx.x;   // input column
    int y0 = blockIdx.y * 32;                 // input row base
#pragma unroll
    for (int i = threadIdx.y; i < 32; i += 8)
        tile[i][threadIdx.x] = in[(size_t)(y0 + i) * INDIM + x];
    __syncthreads();
    int b  = blockIdx.y * 32 + threadIdx.x;   // batch index (contig in inT)
    int c0 = blockIdx.x * 32;
#pragma unroll
    for (int i = threadIdx.y; i < 32; i += 8)
        g_inT[(size_t)(c0 + i) * BATCH + b] = tile[threadIdx.x][i];
}

// -------- 4. main SpMM (L1-resident batch tile of 32) --------
// One 1024-thread CTA per 32-batch tile (grid = 128 ~= #SMs). The CTA's gather
// working set is 1024 rows x 128B = 128KB -> stays resident in L1, so L2 sees
// each line once (16MB total) instead of every gather (855MB).
// Warp = 4 octets; each octet gathers the 128B slice for a DIFFERENT nnz
// (LDG.128/lane, 4 rows x 128B per warp-load, zero waste). Octet partials are
// reduced with shfl_xor, staged in smem 8 cols at a time, stored coalesced.
__global__ void __launch_bounds__(1024, 1) k_spmm(const float* __restrict__ bias,
                                                  float* __restrict__ out) {
    __shared__ float sbuf[32][8][36];          // [warp][col][batch-local], padded
    int w = threadIdx.x >> 5, lane = threadIdx.x & 31;
    int oct = lane >> 3, ol = lane & 7;
    int tb = blockIdx.x;                       // batch tile 0..127
    int b0 = tb * 32;
    int f4base = tb * 8 + ol;                  // float4 index within an inT row
    const float4* inT4 = (const float4*)g_inT;

    for (int half = 0; half < 4; half++) {     // warp covers 32 cols, 8 per flush
        int cbase = w * 32 + half * 8;
#pragma unroll 1
        for (int cc = 0; cc < 8; cc++) {
            int o = cbase + cc;
            int cnt = g_cnt[o];
            cnt = cnt < ELL_PAD ? cnt : ELL_PAD;
            const uint2* mb = &g_meta[o * ELL_PAD];
            float4 a = make_float4(0.f, 0.f, 0.f, 0.f);
            for (int j0 = 0; j0 < cnt; j0 += 32) {
                int n = cnt - j0; n = n < 32 ? n : 32;
                uint2 m = make_uint2(0u, 0u);
                if (lane < n) m = __ldg(&mb[j0 + lane]);
                for (int k = 0; k < n; k += 4) {
                    int slot = k + oct;
                    unsigned ci = __shfl_sync(0xffffffffu, m.y, slot);
                    float wt = __uint_as_float(__shfl_sync(0xffffffffu, m.x, slot));
                    if (slot < n) {
                        float4 x = __ldg(&inT4[(ci << 10) + f4base]);
                        a.x = fmaf(wt, x.x, a.x); a.y = fmaf(wt, x.y, a.y);
                        a.z = fmaf(wt, x.z, a.z); a.w = fmaf(wt, x.w, a.w);
                    }
                }
            }
            // combine the 4 octet partials (each octet holds all 32 batches? no:
            // octet j holds partial over its nnz subset for batches ol*4..ol*4+3)
            a.x += __shfl_xor_sync(0xffffffffu, a.x, 8);
            a.y += __shfl_xor_sync(0xffffffffu, a.y, 8);
            a.z += __shfl_xor_sync(0xffffffffu, a.z, 8);
            a.w += __shfl_xor_sync(0xffffffffu, a.w, 8);
            a.x += __shfl_xor_sync(0xffffffffu, a.x, 16);
            a.y += __shfl_xor_sync(0xffffffffu, a.y, 16);
            a.z += __shfl_xor_sync(0xffffffffu, a.z, 16);
            a.w += __shfl_xor_sync(0xffffffffu, a.w, 16);
            if (oct == 0)
                *(float4*)&sbuf[w][cc][ol * 4] = a;
        }
        __syncwarp();
        // flush 8 cols x 32 rows, coalesced 32B row segments
        {
            int c = lane & 7;
            int rb = lane >> 3;
            float bv = __ldg(&bias[cbase + c]);
#pragma unroll
            for (int p = 0; p < 8; p++) {
                int r = p * 4 + rb;
                out[(size_t)(b0 + r) * OUTDIM + cbase + c] = sbuf[w][c][r] + bv;
            }
        }
        __syncwarp();
    }
}

// -------- launch --------
extern "C" void kernel_launch(void* const* d_in, const int* in_sizes, int n_in,
                              void* d_out, int out_size) {
    const float* input  = (const float*)d_in[0];
    const float* weight = (const float*)d_in[1];
    const float* bias   = (const float*)d_in[2];
    const int*   ind_in = (const int*)d_in[3];
    const int*   ind_out= (const int*)d_in[4];
    int nnz = in_sizes[1];
    float* out = (float*)d_out;

    k_zero<<<1, OUTDIM>>>();
    k_fill<<<(nnz + 255) / 256, 256>>>(ind_in, ind_out, weight, nnz);
    k_transpose<<<dim3(INDIM / 32, BATCH / 32), dim3(32, 8)>>>(input);
    k_spmm<<<BATCH / 32, 1024>>>(bias, out);
}

// round 5
// speedup vs baseline: 1.0347x; 1.0347x over previous
#include <cuda_runtime.h>
#include <stdint.h>

#define BATCH 4096
#define INDIM 1024
#define OUTDIM 1024
#define ELL_PAD 128            // slots per output column (mean 51, ~11 sigma headroom)

// -------- device scratch (static; no allocations allowed) --------
__device__ float g_inT[(size_t)INDIM * BATCH];          // transposed input, 16MB
__device__ uint2 g_meta[(size_t)OUTDIM * ELL_PAD];      // ELL: {weight bits, ind_in} per out col
__device__ int   g_cnt[OUTDIM];

// -------- 1. zero per-column counters --------
__global__ void k_zero() {
    g_cnt[threadIdx.x] = 0;
}

// -------- 2. ELL fill: one atomic gives the slot directly --------
__global__ void k_fill(const int* __restrict__ ind_in, const int* __restrict__ ind_out,
                       const float* __restrict__ wgt, int nnz) {
    int i = blockIdx.x * blockDim.x + threadIdx.x;
    if (i < nnz) {
        int o = ind_out[i];
        int r = atomicAdd(&g_cnt[o], 1);
        if (r < ELL_PAD)
            g_meta[o * ELL_PAD + r] = make_uint2(__float_as_uint(wgt[i]), (unsigned)ind_in[i]);
    }
}

// -------- 3. transpose input [4096,1024] -> inT [1024,4096] --------
__global__ void k_transpose(const float* __restrict__ in) {
    __shared__ float tile[32][33];
    int x  = blockIdx.x * 32 + threadIdx.x;   // input column
    int y0 = blockIdx.y * 32;                 // input row base
#pragma unroll
    for (int i = threadIdx.y; i < 32; i += 8)
        tile[i][threadIdx.x] = __ldcs(&in[(size_t)(y0 + i) * INDIM + x]);
    __syncthreads();
    int b  = blockIdx.y * 32 + threadIdx.x;   // batch index (contig in inT)
    int c0 = blockIdx.x * 32;
#pragma unroll
    for (int i = threadIdx.y; i < 32; i += 8)
        g_inT[(size_t)(c0 + i) * BATCH + b] = tile[threadIdx.x][i];
}

// -------- 4. main SpMM (L1-resident batch tile of 32, shuffle-free inner loop) --------
// One 1024-thread CTA per 32-batch tile (grid=128). Gather working set per CTA
// = 1024 rows x 128B = 128KB -> L1-resident; L2 sees each line ~once.
// Warp = 4 octets; iteration i of a 32-nnz chunk processes slots i*4+oct:
//   meta:  LDG.64 mb[j0+i*4+oct]  (4 addrs/warp, 32B contiguous, octet-broadcast,
//          __ldcs evict-first so the 417KB/CTA meta stream can't evict inT lines)
//   data:  LDG.128 of the nnz row's 128B batch slice (exactly 1 wavefront/nnz)
// No shuffles in the hot loop; full chunks are unrolled and predicate-free.
// Octet partials reduced with 2 shfl_xor at the end of each column only.
__global__ void __launch_bounds__(1024, 1) k_spmm(const float* __restrict__ bias,
                                                  float* __restrict__ out) {
    __shared__ float sbuf[32][8][36];          // [warp][col][batch-local], padded
    int w = threadIdx.x >> 5, lane = threadIdx.x & 31;
    int oct = lane >> 3, ol = lane & 7;
    int tb = blockIdx.x;                       // batch tile 0..127
    int b0 = tb * 32;
    int f4base = tb * 8 + ol;                  // float4 index within an inT row
    const float4* inT4 = (const float4*)g_inT;

    for (int half = 0; half < 4; half++) {     // warp covers 32 cols, 8 per flush
        int cbase = w * 32 + half * 8;
#pragma unroll 1
        for (int cc = 0; cc < 8; cc++) {
            int o = cbase + cc;
            int cnt = g_cnt[o];
            cnt = cnt < ELL_PAD ? cnt : ELL_PAD;
            const uint2* mb = &g_meta[o * ELL_PAD];
            float4 a0 = make_float4(0.f, 0.f, 0.f, 0.f);
            float4 a1 = make_float4(0.f, 0.f, 0.f, 0.f);
            int nfull = cnt & ~31;
            // ---- full 32-nnz chunks: predicate-free, unrolled ----
#pragma unroll 1
            for (int j0 = 0; j0 < nfull; j0 += 32) {
#pragma unroll
                for (int i = 0; i < 8; i += 2) {
                    uint2 m0 = __ldcs(&mb[j0 + i * 4 + oct]);
                    uint2 m1 = __ldcs(&mb[j0 + i * 4 + 4 + oct]);
                    float4 x0 = __ldg(&inT4[(m0.y << 10) + f4base]);
                    float4 x1 = __ldg(&inT4[(m1.y << 10) + f4base]);
                    float w0 = __uint_as_float(m0.x);
                    float w1 = __uint_as_float(m1.x);
                    a0.x = fmaf(w0, x0.x, a0.x); a0.y = fmaf(w0, x0.y, a0.y);
                    a0.z = fmaf(w0, x0.z, a0.z); a0.w = fmaf(w0, x0.w, a0.w);
                    a1.x = fmaf(w1, x1.x, a1.x); a1.y = fmaf(w1, x1.y, a1.y);
                    a1.z = fmaf(w1, x1.z, a1.z); a1.w = fmaf(w1, x1.w, a1.w);
                }
            }
            // ---- remainder (<32 nnz): masked, index-clamped ----
            int rem = cnt - nfull;
#pragma unroll 1
            for (int i4 = 0; i4 < rem; i4 += 4) {
                int slot = i4 + oct;
                uint2 m = __ldcs(&mb[nfull + slot]);   // within ELL_PAD, safe memory
                unsigned ci = m.y & 1023u;             // clamp poison indices
                float wt = (slot < rem) ? __uint_as_float(m.x) : 0.f;
                float4 x = __ldg(&inT4[(ci << 10) + f4base]);
                a0.x = fmaf(wt, x.x, a0.x); a0.y = fmaf(wt, x.y, a0.y);
                a0.z = fmaf(wt, x.z, a0.z); a0.w = fmaf(wt, x.w, a0.w);
            }
            float4 a = make_float4(a0.x + a1.x, a0.y + a1.y, a0.z + a1.z, a0.w + a1.w);
            // combine 4 octet partials
            a.x += __shfl_xor_sync(0xffffffffu, a.x, 8);
            a.y += __shfl_xor_sync(0xffffffffu, a.y, 8);
            a.z += __shfl_xor_sync(0xffffffffu, a.z, 8);
            a.w += __shfl_xor_sync(0xffffffffu, a.w, 8);
            a.x += __shfl_xor_sync(0xffffffffu, a.x, 16);
            a.y += __shfl_xor_sync(0xffffffffu, a.y, 16);
            a.z += __shfl_xor_sync(0xffffffffu, a.z, 16);
            a.w += __shfl_xor_sync(0xffffffffu, a.w, 16);
            if (oct == 0)
                *(float4*)&sbuf[w][cc][ol * 4] = a;
        }
        __syncwarp();
        // flush 8 cols x 32 rows, coalesced 32B row segments
        {
            int c = lane & 7;
            int rb = lane >> 3;
            float bv = __ldg(&bias[cbase + c]);
#pragma unroll
            for (int p = 0; p < 8; p++) {
                int r = p * 4 + rb;
                out[(size_t)(b0 + r) * OUTDIM + cbase + c] = sbuf[w][c][r] + bv;
            }
        }
        __syncwarp();
    }
}

// -------- launch --------
extern "C" void kernel_launch(void* const* d_in, const int* in_sizes, int n_in,
                              void* d_out, int out_size) {
    const float* input  = (const float*)d_in[0];
    const float* weight = (const float*)d_in[1];
    const float* bias   = (const float*)d_in[2];
    const int*   ind_in = (const int*)d_in[3];
    const int*   ind_out= (const int*)d_in[4];
    int nnz = in_sizes[1];
    float* out = (float*)d_out;

    k_zero<<<1, OUTDIM>>>();
    k_fill<<<(nnz + 255) / 256, 256>>>(ind_in, ind_out, weight, nnz);
    k_transpose<<<dim3(INDIM / 32, BATCH / 32), dim3(32, 8)>>>(input);
    k_spmm<<<BATCH / 32, 1024>>>(bias, out);
}

// round 6
// speedup vs baseline: 1.2075x; 1.1670x over previous
#include <cuda_runtime.h>
#include <stdint.h>

#define BATCH 4096
#define INDIM 1024
#define OUTDIM 1024
#define ELL_PAD 128            // slots per output column (mean 51, ~11 sigma headroom)

// -------- device scratch (static; no allocations allowed) --------
__device__ float g_inT[(size_t)INDIM * BATCH];          // transposed input, 16MB
__device__ uint2 g_meta[(size_t)OUTDIM * ELL_PAD];      // ELL: {weight bits, ind_in} per out col
__device__ int   g_cnt[OUTDIM];

// -------- 1. zero per-column counters --------
__global__ void k_zero() {
    g_cnt[threadIdx.x] = 0;
}

// -------- 2. ELL fill: one atomic gives the slot directly --------
__global__ void k_fill(const int* __restrict__ ind_in, const int* __restrict__ ind_out,
                       const float* __restrict__ wgt, int nnz) {
    int i = blockIdx.x * blockDim.x + threadIdx.x;
    if (i < nnz) {
        int o = ind_out[i];
        int r = atomicAdd(&g_cnt[o], 1);
        if (r < ELL_PAD)
            g_meta[o * ELL_PAD + r] = make_uint2(__float_as_uint(wgt[i]), (unsigned)ind_in[i]);
    }
}

// -------- 3. transpose input [4096,1024] -> inT [1024,4096] --------
__global__ void k_transpose(const float* __restrict__ in) {
    __shared__ float tile[32][33];
    int x  = blockIdx.x * 32 + threadIdx.x;   // input column
    int y0 = blockIdx.y * 32;                 // input row base
#pragma unroll
    for (int i = threadIdx.y; i < 32; i += 8)
        tile[i][threadIdx.x] = __ldcs(&in[(size_t)(y0 + i) * INDIM + x]);
    __syncthreads();
    int b  = blockIdx.y * 32 + threadIdx.x;   // batch index (contig in inT)
    int c0 = blockIdx.x * 32;
#pragma unroll
    for (int i = threadIdx.y; i < 32; i += 8)
        g_inT[(size_t)(c0 + i) * BATCH + b] = tile[threadIdx.x][i];
}

// -------- 4. main SpMM (L1-resident gather + full-column meta prefetch) --------
// One 1024-thread CTA per 32-batch tile (grid=128); gather working set
// 1024 rows x 128B = 128KB, L1-resident. Each warp owns 32 output columns and
// keeps the NEXT column's meta (slots 0..63, 2 uint2/lane) in registers,
// fetched one full column ahead so the ~240cyc L2 meta latency is hidden
// behind the current column's ~51 gathers. Meta is distributed by shfl of
// resident registers (no memory dependence). Each octet (8 lanes) gathers
// the 128B batch slice of a different nnz: one LDG.128 wavefront per nnz.
__global__ void __launch_bounds__(1024, 1) k_spmm(const float* __restrict__ bias,
                                                  float* __restrict__ out) {
    __shared__ float sbuf[32][8][36];          // [warp][col][batch-local], padded
    int w = threadIdx.x >> 5, lane = threadIdx.x & 31;
    int oct = lane >> 3, ol = lane & 7;
    int tb = blockIdx.x;                       // batch tile 0..127
    int b0 = tb * 32;
    int f4base = tb * 8 + ol;                  // float4 index within an inT row
    const float4* inT4 = (const float4*)g_inT;
    const unsigned FULL = 0xffffffffu;

    int o_first = w * 32;
    // prefetch column 0 of this warp
    int cntN = g_cnt[o_first]; cntN = cntN < ELL_PAD ? cntN : ELL_PAD;
    uint2 mN0 = __ldcs(&g_meta[o_first * ELL_PAD + lane]);
    uint2 mN1 = __ldcs(&g_meta[o_first * ELL_PAD + 32 + lane]);

#pragma unroll 1
    for (int idx = 0; idx < 32; idx++) {
        int o = w * 32 + idx;
        int cnt = cntN;
        uint2 m0 = mN0, m1 = mN1;
        // issue next column's meta loads NOW (latency hidden by this column)
        if (idx < 31) {
            int on = o + 1;
            cntN = __ldg(&g_cnt[on]); cntN = cntN < ELL_PAD ? cntN : ELL_PAD;
            mN0 = __ldcs(&g_meta[on * ELL_PAD + lane]);
            mN1 = __ldcs(&g_meta[on * ELL_PAD + 32 + lane]);
        }

        float4 a0 = make_float4(0.f, 0.f, 0.f, 0.f);
        float4 a1 = make_float4(0.f, 0.f, 0.f, 0.f);

        // ---- chunk 0 (slots 0..31) from m0 ----
        {
            int n = cnt < 32 ? cnt : 32;
            if (n == 32) {
#pragma unroll
                for (int k = 0; k < 32; k += 8) {
                    int s0 = k + oct, s1 = k + 4 + oct;
                    unsigned ci0 = __shfl_sync(FULL, m0.y, s0);
                    float   wt0 = __uint_as_float(__shfl_sync(FULL, m0.x, s0));
                    unsigned ci1 = __shfl_sync(FULL, m0.y, s1);
                    float   wt1 = __uint_as_float(__shfl_sync(FULL, m0.x, s1));
                    float4 x0 = __ldg(&inT4[(ci0 << 10) + f4base]);
                    float4 x1 = __ldg(&inT4[(ci1 << 10) + f4base]);
                    a0.x = fmaf(wt0, x0.x, a0.x); a0.y = fmaf(wt0, x0.y, a0.y);
                    a0.z = fmaf(wt0, x0.z, a0.z); a0.w = fmaf(wt0, x0.w, a0.w);
                    a1.x = fmaf(wt1, x1.x, a1.x); a1.y = fmaf(wt1, x1.y, a1.y);
                    a1.z = fmaf(wt1, x1.z, a1.z); a1.w = fmaf(wt1, x1.w, a1.w);
                }
            } else {
#pragma unroll
                for (int k = 0; k < 32; k += 4) {
                    if (k >= n) break;                    // warp-uniform
                    int s = k + oct;
                    unsigned ci = __shfl_sync(FULL, m0.y, s) & 1023u;
                    float   wt = __uint_as_float(__shfl_sync(FULL, m0.x, s));
                    if (s < n) {
                        float4 x = __ldg(&inT4[(ci << 10) + f4base]);
                        a0.x = fmaf(wt, x.x, a0.x); a0.y = fmaf(wt, x.y, a0.y);
                        a0.z = fmaf(wt, x.z, a0.z); a0.w = fmaf(wt, x.w, a0.w);
                    }
                }
            }
        }
        // ---- chunk 1 (slots 32..63) from m1 ----
        if (cnt > 32) {
            int n = cnt - 32; n = n < 32 ? n : 32;
            if (n == 32) {
#pragma unroll
                for (int k = 0; k < 32; k += 8) {
                    int s0 = k + oct, s1 = k + 4 + oct;
                    unsigned ci0 = __shfl_sync(FULL, m1.y, s0);
                    float   wt0 = __uint_as_float(__shfl_sync(FULL, m1.x, s0));
                    unsigned ci1 = __shfl_sync(FULL, m1.y, s1);
                    float   wt1 = __uint_as_float(__shfl_sync(FULL, m1.x, s1));
                    float4 x0 = __ldg(&inT4[(ci0 << 10) + f4base]);
                    float4 x1 = __ldg(&inT4[(ci1 << 10) + f4base]);
                    a0.x = fmaf(wt0, x0.x, a0.x); a0.y = fmaf(wt0, x0.y, a0.y);
                    a0.z = fmaf(wt0, x0.z, a0.z); a0.w = fmaf(wt0, x0.w, a0.w);
                    a1.x = fmaf(wt1, x1.x, a1.x); a1.y = fmaf(wt1, x1.y, a1.y);
                    a1.z = fmaf(wt1, x1.z, a1.z); a1.w = fmaf(wt1, x1.w, a1.w);
                }
            } else {
#pragma unroll
                for (int k = 0; k < 32; k += 4) {
                    if (k >= n) break;
                    int s = k + oct;
                    unsigned ci = __shfl_sync(FULL, m1.y, s) & 1023u;
                    float   wt = __uint_as_float(__shfl_sync(FULL, m1.x, s));
                    if (s < n) {
                        float4 x = __ldg(&inT4[(ci << 10) + f4base]);
                        a0.x = fmaf(wt, x.x, a0.x); a0.y = fmaf(wt, x.y, a0.y);
                        a0.z = fmaf(wt, x.z, a0.z); a0.w = fmaf(wt, x.w, a0.w);
                    }
                }
            }
        }
        // ---- rare tail: cnt > 64 (chunks 2-3), inline meta load ----
        if (cnt > 64) {
#pragma unroll 1
            for (int q = 2; q < 4; q++) {
                int n = cnt - q * 32;
                if (n <= 0) break;
                n = n < 32 ? n : 32;
                uint2 mq = __ldcs(&g_meta[o * ELL_PAD + q * 32 + lane]);
#pragma unroll
                for (int k = 0; k < 32; k += 4) {
                    if (k >= n) break;
                    int s = k + oct;
                    unsigned ci = __shfl_sync(FULL, mq.y, s) & 1023u;
                    float   wt = __uint_as_float(__shfl_sync(FULL, mq.x, s));
                    if (s < n) {
                        float4 x = __ldg(&inT4[(ci << 10) + f4base]);
                        a0.x = fmaf(wt, x.x, a0.x); a0.y = fmaf(wt, x.y, a0.y);
                        a0.z = fmaf(wt, x.z, a0.z); a0.w = fmaf(wt, x.w, a0.w);
                    }
                }
            }
        }

        float4 a = make_float4(a0.x + a1.x, a0.y + a1.y, a0.z + a1.z, a0.w + a1.w);
        // combine 4 octet partials
        a.x += __shfl_xor_sync(FULL, a.x, 8);
        a.y += __shfl_xor_sync(FULL, a.y, 8);
        a.z += __shfl_xor_sync(FULL, a.z, 8);
        a.w += __shfl_xor_sync(FULL, a.w, 8);
        a.x += __shfl_xor_sync(FULL, a.x, 16);
        a.y += __shfl_xor_sync(FULL, a.y, 16);
        a.z += __shfl_xor_sync(FULL, a.z, 16);
        a.w += __shfl_xor_sync(FULL, a.w, 16);
        if (oct == 0)
            *(float4*)&sbuf[w][idx & 7][ol * 4] = a;

        // flush every 8 columns: coalesced 32B row segments
        if ((idx & 7) == 7) {
            __syncwarp();
            int cbase = w * 32 + (idx & ~7);
            int c = lane & 7;
            int rb = lane >> 3;
            float bv = __ldg(&bias[cbase + c]);
#pragma unroll
            for (int p = 0; p < 8; p++) {
                int r = p * 4 + rb;
                out[(size_t)(b0 + r) * OUTDIM + cbase + c] = sbuf[w][c][r] + bv;
            }
            __syncwarp();
        }
    }
}

// -------- launch --------
extern "C" void kernel_launch(void* const* d_in, const int* in_sizes, int n_in,
                              void* d_out, int out_size) {
    const float* input  = (const float*)d_in[0];
    const float* weight = (const float*)d_in[1];
    const float* bias   = (const float*)d_in[2];
    const int*   ind_in = (const int*)d_in[3];
    const int*   ind_out= (const int*)d_in[4];
    int nnz = in_sizes[1];
    float* out = (float*)d_out;

    k_zero<<<1, OUTDIM>>>();
    k_fill<<<(nnz + 255) / 256, 256>>>(ind_in, ind_out, weight, nnz);
    k_transpose<<<dim3(INDIM / 32, BATCH / 32), dim3(32, 8)>>>(input);
    k_spmm<<<BATCH / 32, 1024>>>(bias, out);
}